// round 3
// baseline (speedup 1.0000x reference)
#include <cuda_runtime.h>
#include <math.h>
#include <stdint.h>

// Problem dims
#define BATCH 32
#define NV    2048
#define NS    512
#define LSEQ  64
#define FEAT  1024
#define SEM   512
#define HID   512
#define ATTD  512
#define DM    512
#define CIN   (FEAT + SEM)   // 1536
#define COUT  FEAT           // 1024

// Output layout in d_out (flattened tuple): ctx [B,1024], v_attn [B,2048], s_attn [B,512]
#define OUT_CTX_OFF   0
#define OUT_VATT_OFF  (BATCH * COUT)                 // 32768
#define OUT_SATT_OFF  (OUT_VATT_OFF + BATCH * NV)    // 98304

// Scratch (device globals; no allocation allowed)
__device__ float g_pm[BATCH * DM];
__device__ float g_base_v[BATCH * ATTD];
__device__ float g_base_s[BATCH * ATTD];
__device__ float g_vscores[BATCH * NV];
__device__ float g_sscores[BATCH * NS];
__device__ float g_ctx[BATCH * CIN];

// ---------------------------------------------------------------------------
// 1) mean over patient sequence: g_pm[b][d] = mean_l PI[b,l,d]
// ---------------------------------------------------------------------------
__global__ void k_mean(const float* __restrict__ PI) {
    int b = blockIdx.x;
    int d = threadIdx.x;
    const float* p = PI + (size_t)b * LSEQ * DM + d;
    float s = 0.f;
#pragma unroll
    for (int l = 0; l < LSEQ; l++) s += p[(size_t)l * DM];
    g_pm[b * DM + d] = s * (1.0f / LSEQ);
}

// ---------------------------------------------------------------------------
// 2) base vectors: pinfo = pm@W3+b3 ; base_v = q@W1v + pinfo ; base_s = q@W1s + pinfo
// ---------------------------------------------------------------------------
__global__ void k_base(const float* __restrict__ query,
                       const float* __restrict__ W1v,
                       const float* __restrict__ W1s,
                       const float* __restrict__ W3,
                       const float* __restrict__ b3) {
    int b = blockIdx.x;
    int a = threadIdx.x;                 // 512 threads
    __shared__ float sq[HID];
    __shared__ float sp[DM];
    sq[a] = query[b * HID + a];
    sp[a] = g_pm[b * DM + a];
    __syncthreads();
    float ap = 0.f, av = 0.f, as = 0.f;
#pragma unroll 8
    for (int d = 0; d < DM; d++) {
        float pd = sp[d], qd = sq[d];
        ap = fmaf(pd, W3 [d * ATTD + a], ap);
        av = fmaf(qd, W1v[d * ATTD + a], av);
        as = fmaf(qd, W1s[d * ATTD + a], as);
    }
    float pin = ap + b3[a];
    g_base_v[b * ATTD + a] = pin + av;
    g_base_s[b * ATTD + a] = pin + as;
}

// ---------------------------------------------------------------------------
// 3) fused score GEMM: scores[row] = sum_c tanh( (X@W2)[row,c] + base[b,c] ) * v[c]
//    Block: 256 thr, TM=32 rows, N=512 cols fully in registers (64 acc/thread).
//    Warp w owns rows w*4..w*4+3; lane tx owns cols {tx*4 + 128*ch + j}.
// ---------------------------------------------------------------------------
template <int K, int ROWS_PER_BATCH>
__global__ __launch_bounds__(256) void k_scores(const float* __restrict__ X,
                                                const float* __restrict__ W2,
                                                const float* __restrict__ base,
                                                const float* __restrict__ vvec,
                                                float* __restrict__ scores) {
    const int TM = 32, KC = 16;
    __shared__ float sA[KC][36];         // padded: store conflicts 2-way, reads broadcast
    __shared__ float sB[KC][ATTD];
    __shared__ float s_base[ATTD];
    __shared__ float s_vv[ATTD];

    int tid = threadIdx.x;
    int tx = tid & 31, ty = tid >> 5;
    int row0 = blockIdx.x * TM;
    int b = row0 / ROWS_PER_BATCH;

    s_base[tid]       = base[b * ATTD + tid];
    s_base[tid + 256] = base[b * ATTD + tid + 256];
    s_vv[tid]         = vvec[tid];
    s_vv[tid + 256]   = vvec[tid + 256];

    float acc[4][16];
#pragma unroll
    for (int i = 0; i < 4; i++)
#pragma unroll
        for (int j = 0; j < 16; j++) acc[i][j] = 0.f;

    const float* Xblk = X + (size_t)row0 * K;

    for (int k0 = 0; k0 < K; k0 += KC) {
        __syncthreads();
        // A tile: 32 rows x 16 k (512 floats). Each thread: float2.
        {
            int r  = tid >> 3;
            int kk = (tid & 7) * 2;
            float2 v2 = *(const float2*)(Xblk + (size_t)r * K + k0 + kk);
            sA[kk][r]     = v2.x;
            sA[kk + 1][r] = v2.y;
        }
        // B tile: 16 x 512 (2048 float4). Each thread: 8 float4, coalesced.
#pragma unroll
        for (int j = 0; j < 8; j++) {
            int idx = tid + j * 256;       // 0..2047
            int kk  = idx >> 7;            // /128
            int c4  = idx & 127;
            *(float4*)&sB[kk][c4 * 4] =
                *(const float4*)(W2 + (size_t)(k0 + kk) * ATTD + c4 * 4);
        }
        __syncthreads();
#pragma unroll
        for (int kk = 0; kk < KC; kk++) {
            float4 av = *(const float4*)&sA[kk][ty * 4];
            float ar[4] = {av.x, av.y, av.z, av.w};
#pragma unroll
            for (int ch = 0; ch < 4; ch++) {
                float4 bv = *(const float4*)&sB[kk][tx * 4 + ch * 128];
                float br[4] = {bv.x, bv.y, bv.z, bv.w};
#pragma unroll
                for (int i = 0; i < 4; i++)
#pragma unroll
                    for (int j = 0; j < 4; j++)
                        acc[i][ch * 4 + j] = fmaf(ar[i], br[j], acc[i][ch * 4 + j]);
            }
        }
    }

    // Epilogue: tanh + vv dot, warp-reduce across lanes (cols)
#pragma unroll
    for (int i = 0; i < 4; i++) {
        float part = 0.f;
#pragma unroll
        for (int ch = 0; ch < 4; ch++) {
#pragma unroll
            for (int j = 0; j < 4; j++) {
                int c = tx * 4 + ch * 128 + j;
                part = fmaf(tanhf(acc[i][ch * 4 + j] + s_base[c]), s_vv[c], part);
            }
        }
#pragma unroll
        for (int off = 16; off > 0; off >>= 1)
            part += __shfl_down_sync(0xFFFFFFFFu, part, off);
        if (tx == 0) scores[row0 + ty * 4 + i] = part;
    }
}

// ---------------------------------------------------------------------------
// 4) softmax over n per batch; writes attn into output region
// ---------------------------------------------------------------------------
template <int N>
__global__ __launch_bounds__(256) void k_softmax(const float* __restrict__ scores,
                                                 float* __restrict__ attn_out) {
    const int PER = N / 256;
    int b = blockIdx.x;
    int tid = threadIdx.x;
    __shared__ float red[8];

    float v[PER];
    float m = -INFINITY;
#pragma unroll
    for (int j = 0; j < PER; j++) {
        v[j] = scores[b * N + tid + j * 256];
        m = fmaxf(m, v[j]);
    }
#pragma unroll
    for (int off = 16; off > 0; off >>= 1)
        m = fmaxf(m, __shfl_xor_sync(0xFFFFFFFFu, m, off));
    if ((tid & 31) == 0) red[tid >> 5] = m;
    __syncthreads();
    m = fmaxf(fmaxf(fmaxf(red[0], red[1]), fmaxf(red[2], red[3])),
              fmaxf(fmaxf(red[4], red[5]), fmaxf(red[6], red[7])));

    float s = 0.f;
#pragma unroll
    for (int j = 0; j < PER; j++) {
        v[j] = expf(v[j] - m);
        s += v[j];
    }
#pragma unroll
    for (int off = 16; off > 0; off >>= 1)
        s += __shfl_xor_sync(0xFFFFFFFFu, s, off);
    __syncthreads();
    if ((tid & 31) == 0) red[tid >> 5] = s;
    __syncthreads();
    s = red[0] + red[1] + red[2] + red[3] + red[4] + red[5] + red[6] + red[7];
    float inv = 1.0f / s;
#pragma unroll
    for (int j = 0; j < PER; j++)
        attn_out[b * N + tid + j * 256] = v[j] * inv;
}

// ---------------------------------------------------------------------------
// 5) attention-weighted sum: g_ctx[b, coff+f] = sum_i X[b,i,f] * attn[b,i]
//    grid: (F/256, B); DRAM-bound streaming of X.
// ---------------------------------------------------------------------------
template <int N, int F>
__global__ __launch_bounds__(256) void k_wsum(const float* __restrict__ X,
                                              const float* __restrict__ attn,
                                              int coff) {
    __shared__ float sat[N];
    int b = blockIdx.y;
    int tid = threadIdx.x;
    int f = blockIdx.x * 256 + tid;
#pragma unroll
    for (int j = 0; j < N / 256; j++)
        sat[tid + j * 256] = attn[b * N + tid + j * 256];
    __syncthreads();
    const float* Xb = X + (size_t)b * N * F + f;
    float acc = 0.f;
#pragma unroll 4
    for (int i = 0; i < N; i++)
        acc = fmaf(Xb[(size_t)i * F], sat[i], acc);
    g_ctx[b * CIN + coff + f] = acc;
}

// ---------------------------------------------------------------------------
// 6) final GEMM: out_ctx[32,1024] = g_ctx[32,1536] @ W[1536,1024] + bW
//    grid 8 (col tiles of 128), 256 threads, thread tile 4x4
// ---------------------------------------------------------------------------
__global__ __launch_bounds__(256) void k_final(const float* __restrict__ W,
                                               const float* __restrict__ bW,
                                               float* __restrict__ out) {
    const int KC = 32;
    __shared__ float sXT[KC][36];     // transposed [k][row]
    __shared__ float sW[KC][128];
    int tid = threadIdx.x;
    int tx = tid & 31, ty = tid >> 5;
    int c0 = blockIdx.x * 128;

    float acc[4][4];
#pragma unroll
    for (int i = 0; i < 4; i++)
#pragma unroll
        for (int j = 0; j < 4; j++) acc[i][j] = 0.f;

    for (int k0 = 0; k0 < CIN; k0 += KC) {
        __syncthreads();
        {   // X tile: 32 rows x 32 k
            int r  = tid >> 3;
            int kk = (tid & 7) * 4;
            float4 v4 = *(const float4*)(g_ctx + (size_t)r * CIN + k0 + kk);
            sXT[kk][r] = v4.x; sXT[kk + 1][r] = v4.y;
            sXT[kk + 2][r] = v4.z; sXT[kk + 3][r] = v4.w;
        }
#pragma unroll
        for (int j = 0; j < 4; j++) {   // W tile: 32 x 128 (1024 float4)
            int idx = tid + j * 256;
            int kk = idx >> 5;
            int c4 = idx & 31;
            *(float4*)&sW[kk][c4 * 4] =
                *(const float4*)(W + (size_t)(k0 + kk) * COUT + c0 + c4 * 4);
        }
        __syncthreads();
#pragma unroll
        for (int kk = 0; kk < KC; kk++) {
            float4 av = *(const float4*)&sXT[kk][ty * 4];
            float4 bv = *(const float4*)&sW[kk][tx * 4];
            float ar[4] = {av.x, av.y, av.z, av.w};
            float br[4] = {bv.x, bv.y, bv.z, bv.w};
#pragma unroll
            for (int i = 0; i < 4; i++)
#pragma unroll
                for (int j = 0; j < 4; j++)
                    acc[i][j] = fmaf(ar[i], br[j], acc[i][j]);
        }
    }
#pragma unroll
    for (int i = 0; i < 4; i++) {
        int r = ty * 4 + i;
#pragma unroll
        for (int j = 0; j < 4; j++) {
            int c = c0 + tx * 4 + j;
            out[(size_t)r * COUT + c] = acc[i][j] + bW[c];
        }
    }
}

// ---------------------------------------------------------------------------
extern "C" void kernel_launch(void* const* d_in, const int* in_sizes, int n_in,
                              void* d_out, int out_size) {
    const float* query = (const float*)d_in[0];
    const float* VF    = (const float*)d_in[1];
    const float* SF    = (const float*)d_in[2];
    const float* PI    = (const float*)d_in[3];
    const float* W1v   = (const float*)d_in[4];
    const float* W2v   = (const float*)d_in[5];
    const float* vv    = (const float*)d_in[6];
    const float* W3    = (const float*)d_in[7];
    const float* b3    = (const float*)d_in[8];
    const float* W1s   = (const float*)d_in[9];
    const float* W2s   = (const float*)d_in[10];
    const float* vs    = (const float*)d_in[11];
    const float* W     = (const float*)d_in[12];
    const float* bW    = (const float*)d_in[13];
    float* out = (float*)d_out;

    float* g_pm_p;      cudaGetSymbolAddress((void**)&g_pm_p, g_pm);
    float* base_v_p;    cudaGetSymbolAddress((void**)&base_v_p, g_base_v);
    float* base_s_p;    cudaGetSymbolAddress((void**)&base_s_p, g_base_s);
    float* vscore_p;    cudaGetSymbolAddress((void**)&vscore_p, g_vscores);
    float* sscore_p;    cudaGetSymbolAddress((void**)&sscore_p, g_sscores);

    float* v_attn = out + OUT_VATT_OFF;
    float* s_attn = out + OUT_SATT_OFF;

    k_mean<<<BATCH, DM>>>(PI);
    k_base<<<BATCH, ATTD>>>(query, W1v, W1s, W3, b3);

    k_scores<FEAT, NV><<<(BATCH * NV) / 32, 256>>>(VF, W2v, base_v_p, vv, vscore_p);
    k_scores<SEM,  NS><<<(BATCH * NS) / 32, 256>>>(SF, W2s, base_s_p, vs, sscore_p);

    k_softmax<NV><<<BATCH, 256>>>(vscore_p, v_attn);
    k_softmax<NS><<<BATCH, 256>>>(sscore_p, s_attn);

    dim3 gv(FEAT / 256, BATCH);
    k_wsum<NV, FEAT><<<gv, 256>>>(VF, v_attn, 0);
    dim3 gs(SEM / 256, BATCH);
    k_wsum<NS, SEM><<<gs, 256>>>(SF, s_attn, FEAT);

    k_final<<<COUT / 128, 256>>>(W, bW, out + OUT_CTX_OFF);
}

// round 6
// speedup vs baseline: 1.8476x; 1.8476x over previous
#include <cuda_runtime.h>
#include <math.h>
#include <stdint.h>

// Problem dims
#define BATCH 32
#define NV    2048
#define NS    512
#define LSEQ  64
#define FEAT  1024
#define SEM   512
#define HID   512
#define ATTD  512
#define DM    512
#define CIN   (FEAT + SEM)   // 1536
#define COUT  FEAT           // 1024

// Output layout in d_out: ctx [B,1024], v_attn [B,2048], s_attn [B,512]
#define OUT_CTX_OFF   0
#define OUT_VATT_OFF  (BATCH * COUT)                 // 32768
#define OUT_SATT_OFF  (OUT_VATT_OFF + BATCH * NV)    // 98304

// Scratch (device globals; no allocation allowed)
__device__ float g_pm[BATCH * DM];
__device__ float g_base_v[BATCH * ATTD];
__device__ float g_base_s[BATCH * ATTD];
__device__ float g_vscores[BATCH * NV];
__device__ float g_sscores[BATCH * NS];
__device__ float g_ctx[BATCH * CIN];

// ===========================================================================
// mma.sync tf32 helpers (portable PTX, works under compute_103 target)
// ===========================================================================
__device__ __forceinline__ float f2tf(float f) {
    uint32_t u;
    asm("cvt.rna.tf32.f32 %0, %1;" : "=r"(u) : "f"(f));
    return __uint_as_float(u);
}

__device__ __forceinline__ void mma8(float* c, const uint4& a, const uint2& b) {
    asm volatile(
        "mma.sync.aligned.m16n8k8.row.col.f32.tf32.tf32.f32 "
        "{%0,%1,%2,%3}, {%4,%5,%6,%7}, {%8,%9}, {%0,%1,%2,%3};"
        : "+f"(c[0]), "+f"(c[1]), "+f"(c[2]), "+f"(c[3])
        : "r"(a.x), "r"(a.y), "r"(a.z), "r"(a.w), "r"(b.x), "r"(b.y));
}

// SMEM float-offsets (dynamic smem)
//  As blocks: [mtile(8)*4 + ks(4)] x 132 floats  (32 lanes x 4 regs, pad 4)
//  Bs blocks: [ks(4)*16 + ntile(16)] x 66 floats (32 lanes x 2 regs, pad 2)
#define MM_ASZ  4224            // 32 * 132
#define MM_BSZ  4224            // 64 * 66
#define MM_BUF  (MM_ASZ + MM_BSZ)            // 8448
#define MM_BASE (2 * MM_BUF)                 // 16896
#define MM_VV   (MM_BASE + 512)
#define MM_RED  (MM_VV + 512)
#define MM_TOT  (MM_RED + 256)               // 18176 floats
#define MM_SMEM_BYTES (MM_TOT * 4)           // 72704 bytes

// ===========================================================================
// Fused score GEMM on tensor cores (mma.sync tf32):
//   scores[row] = sum_c tanh( (X @ W2)[row,c] + base[b,c] ) * vv[c]
// CTA: 256 thr / 8 warps as 4(M)x2(N); M_tile=128; N=512 in 4 chunks of 128.
// K chunked by 32, double-buffered SMEM, fragment-major staging.
// ===========================================================================
template <int K, int RPB>
__global__ void __launch_bounds__(256, 1)
k_scores_mma(const float* __restrict__ X,     // [M_total, K]
             const float* __restrict__ W2,    // [K, 512] row-major
             const float* __restrict__ base,  // [B, 512]
             const float* __restrict__ vvec,  // [512]
             float* __restrict__ scores) {
    constexpr int NCK = K / 32;          // K chunks
    constexpr int IT  = 4 * NCK;         // 4 N-chunks x K chunks
    extern __shared__ float smf[];

    const int tid = threadIdx.x;
    const int l   = tid & 31;
    const int w   = tid >> 5;
    const int wm  = w & 3;               // M group (32 rows)
    const int wn  = w >> 2;              // N half (64 cols)
    const int row0 = blockIdx.x * 128;
    const int b = row0 / RPB;

    // stage base & vv
    smf[MM_BASE + tid]       = base[b * ATTD + tid];
    smf[MM_BASE + tid + 256] = base[b * ATTD + tid + 256];
    smf[MM_VV + tid]         = vvec[tid];
    smf[MM_VV + tid + 256]   = vvec[tid + 256];

    float acc[16][4];
    float part[4] = {0.f, 0.f, 0.f, 0.f};
    float4 pa[4], pb[4];

    const float* Xr = X + (size_t)row0 * K;

    // prefetch chunk 0
    {
        const int k0 = 0, n0 = 0;
#pragma unroll
        for (int i = 0; i < 4; i++) {
            int idx = tid + i * 256;
            pa[i] = *(const float4*)(Xr + (size_t)(idx >> 3) * K + k0 + (idx & 7) * 4);
            pb[i] = *(const float4*)(W2 + (size_t)(k0 + (idx >> 5)) * ATTD + n0 + (idx & 31) * 4);
        }
    }

    for (int it = 0; it < IT; it++) {
        const int q = it / NCK;
        const int c = it - q * NCK;
        float* As = smf + (it & 1) * MM_BUF;
        float* Bs = As + MM_ASZ;

        // ---- store staged chunk (fragment-major, tf32-rounded) ----
#pragma unroll
        for (int i = 0; i < 4; i++) {
            int idx = tid + i * 256;
            {   // A element (r, k = kq*4 + e)
                int r = idx >> 3, kq = idx & 7;
                int blk = (r >> 4) * 4 + (kq >> 1);
                int j = ((r & 15) >> 3) | ((kq & 1) << 1);
                float* dst = As + blk * 132 + ((r & 7) << 4) + j;
                dst[0]  = f2tf(pa[i].x);
                dst[4]  = f2tf(pa[i].y);
                dst[8]  = f2tf(pa[i].z);
                dst[12] = f2tf(pa[i].w);
            }
            {   // B element (kk, n = nq*4 + e)
                int kk = idx >> 5, nq = idx & 31;
                int j = (kk >> 2) & 1;
                int blk = (kk >> 3) * 16 + (nq >> 1);
                float* dst = Bs + blk * 66 + (nq & 1) * 32 + (kk & 3) * 2 + j;
                dst[0]  = f2tf(pb[i].x);
                dst[8]  = f2tf(pb[i].y);
                dst[16] = f2tf(pb[i].z);
                dst[24] = f2tf(pb[i].w);
            }
        }
        __syncthreads();

        // ---- prefetch next chunk ----
        if (it + 1 < IT) {
            const int qn = (it + 1) / NCK;
            const int cn = (it + 1) - qn * NCK;
            const int k0 = cn * 32, n0 = qn * 128;
#pragma unroll
            for (int i = 0; i < 4; i++) {
                int idx = tid + i * 256;
                pa[i] = *(const float4*)(Xr + (size_t)(idx >> 3) * K + k0 + (idx & 7) * 4);
                pb[i] = *(const float4*)(W2 + (size_t)(k0 + (idx >> 5)) * ATTD + n0 + (idx & 31) * 4);
            }
        }

        if (c == 0) {
#pragma unroll
            for (int t = 0; t < 16; t++)
#pragma unroll
                for (int j = 0; j < 4; j++) acc[t][j] = 0.f;
        }

        // ---- compute 4 k-steps ----
#pragma unroll
        for (int ks = 0; ks < 4; ks++) {
            const uint4 A0 = *(const uint4*)(As + ((2 * wm) * 4 + ks) * 132 + l * 4);
            const uint4 A1 = *(const uint4*)(As + ((2 * wm + 1) * 4 + ks) * 132 + l * 4);
#pragma unroll
            for (int t = 0; t < 8; t++) {
                const int nt = wn * 8 + t;
                const uint2 Bv = *(const uint2*)(Bs + (ks * 16 + nt) * 66 + l * 2);
                mma8(acc[t],     A0, Bv);
                mma8(acc[8 + t], A1, Bv);
            }
        }

        // ---- epilogue at end of each N chunk: tanh + vv dot ----
        if (c == NCK - 1) {
#pragma unroll
            for (int t = 0; t < 8; t++) {
                const int n = q * 128 + wn * 64 + t * 8 + (l & 3) * 2;
                const float2 bs = *(const float2*)(smf + MM_BASE + n);
                const float2 vs = *(const float2*)(smf + MM_VV + n);
                part[0] += tanhf(acc[t][0] + bs.x) * vs.x + tanhf(acc[t][1] + bs.y) * vs.y;
                part[1] += tanhf(acc[t][2] + bs.x) * vs.x + tanhf(acc[t][3] + bs.y) * vs.y;
                part[2] += tanhf(acc[8 + t][0] + bs.x) * vs.x + tanhf(acc[8 + t][1] + bs.y) * vs.y;
                part[3] += tanhf(acc[8 + t][2] + bs.x) * vs.x + tanhf(acc[8 + t][3] + bs.y) * vs.y;
            }
        }
    }

    // reduce over the 4 lanes sharing a row (cols within warp)
#pragma unroll
    for (int p = 0; p < 4; p++) {
        part[p] += __shfl_xor_sync(0xFFFFFFFFu, part[p], 1);
        part[p] += __shfl_xor_sync(0xFFFFFFFFu, part[p], 2);
    }
    __syncthreads();
    if ((l & 3) == 0) {
#pragma unroll
        for (int p = 0; p < 4; p++) {
            int rl = wm * 32 + (p >> 1) * 16 + (p & 1) * 8 + (l >> 2);
            smf[MM_RED + rl * 2 + wn] = part[p];
        }
    }
    __syncthreads();
    if (tid < 128)
        scores[row0 + tid] = smf[MM_RED + tid * 2] + smf[MM_RED + tid * 2 + 1];
}

// ---------------------------------------------------------------------------
// 1) mean over patient sequence
// ---------------------------------------------------------------------------
__global__ void k_mean(const float* __restrict__ PI) {
    int b = blockIdx.x;
    int d = threadIdx.x;
    const float* p = PI + (size_t)b * LSEQ * DM + d;
    float s = 0.f;
#pragma unroll
    for (int l = 0; l < LSEQ; l++) s += p[(size_t)l * DM];
    g_pm[b * DM + d] = s * (1.0f / LSEQ);
}

// ---------------------------------------------------------------------------
// 2) base vectors
// ---------------------------------------------------------------------------
__global__ void k_base(const float* __restrict__ query,
                       const float* __restrict__ W1v,
                       const float* __restrict__ W1s,
                       const float* __restrict__ W3,
                       const float* __restrict__ b3) {
    int b = blockIdx.x;
    int a = threadIdx.x;                 // 512 threads
    __shared__ float sq[HID];
    __shared__ float sp[DM];
    sq[a] = query[b * HID + a];
    sp[a] = g_pm[b * DM + a];
    __syncthreads();
    float ap = 0.f, av = 0.f, as = 0.f;
#pragma unroll 8
    for (int d = 0; d < DM; d++) {
        float pd = sp[d], qd = sq[d];
        ap = fmaf(pd, W3 [d * ATTD + a], ap);
        av = fmaf(qd, W1v[d * ATTD + a], av);
        as = fmaf(qd, W1s[d * ATTD + a], as);
    }
    float pin = ap + b3[a];
    g_base_v[b * ATTD + a] = pin + av;
    g_base_s[b * ATTD + a] = pin + as;
}

// ---------------------------------------------------------------------------
// 4) softmax over n per batch; writes attn into output region
// ---------------------------------------------------------------------------
template <int N>
__global__ __launch_bounds__(256) void k_softmax(const float* __restrict__ scores,
                                                 float* __restrict__ attn_out) {
    const int PER = N / 256;
    int b = blockIdx.x;
    int tid = threadIdx.x;
    __shared__ float red[8];

    float v[PER];
    float m = -INFINITY;
#pragma unroll
    for (int j = 0; j < PER; j++) {
        v[j] = scores[b * N + tid + j * 256];
        m = fmaxf(m, v[j]);
    }
#pragma unroll
    for (int off = 16; off > 0; off >>= 1)
        m = fmaxf(m, __shfl_xor_sync(0xFFFFFFFFu, m, off));
    if ((tid & 31) == 0) red[tid >> 5] = m;
    __syncthreads();
    m = fmaxf(fmaxf(fmaxf(red[0], red[1]), fmaxf(red[2], red[3])),
              fmaxf(fmaxf(red[4], red[5]), fmaxf(red[6], red[7])));

    float s = 0.f;
#pragma unroll
    for (int j = 0; j < PER; j++) {
        v[j] = expf(v[j] - m);
        s += v[j];
    }
#pragma unroll
    for (int off = 16; off > 0; off >>= 1)
        s += __shfl_xor_sync(0xFFFFFFFFu, s, off);
    __syncthreads();
    if ((tid & 31) == 0) red[tid >> 5] = s;
    __syncthreads();
    s = red[0] + red[1] + red[2] + red[3] + red[4] + red[5] + red[6] + red[7];
    float inv = 1.0f / s;
#pragma unroll
    for (int j = 0; j < PER; j++)
        attn_out[b * N + tid + j * 256] = v[j] * inv;
}

// ---------------------------------------------------------------------------
// 5) attention-weighted sum
// ---------------------------------------------------------------------------
template <int N, int F>
__global__ __launch_bounds__(256) void k_wsum(const float* __restrict__ X,
                                              const float* __restrict__ attn,
                                              int coff) {
    __shared__ float sat[N];
    int b = blockIdx.y;
    int tid = threadIdx.x;
    int f = blockIdx.x * 256 + tid;
#pragma unroll
    for (int j = 0; j < N / 256; j++)
        sat[tid + j * 256] = attn[b * N + tid + j * 256];
    __syncthreads();
    const float* Xb = X + (size_t)b * N * F + f;
    float acc = 0.f;
#pragma unroll 4
    for (int i = 0; i < N; i++)
        acc = fmaf(Xb[(size_t)i * F], sat[i], acc);
    g_ctx[b * CIN + coff + f] = acc;
}

// ---------------------------------------------------------------------------
// 6) final GEMM: out_ctx[32,1024] = g_ctx[32,1536] @ W[1536,1024] + bW
// ---------------------------------------------------------------------------
__global__ __launch_bounds__(256) void k_final(const float* __restrict__ W,
                                               const float* __restrict__ bW,
                                               float* __restrict__ out) {
    const int KC = 32;
    __shared__ float sXT[KC][36];
    __shared__ float sW[KC][128];
    int tid = threadIdx.x;
    int tx = tid & 31, ty = tid >> 5;
    int c0 = blockIdx.x * 128;

    float acc[4][4];
#pragma unroll
    for (int i = 0; i < 4; i++)
#pragma unroll
        for (int j = 0; j < 4; j++) acc[i][j] = 0.f;

    for (int k0 = 0; k0 < CIN; k0 += KC) {
        __syncthreads();
        {
            int r  = tid >> 3;
            int kk = (tid & 7) * 4;
            float4 v4 = *(const float4*)(g_ctx + (size_t)r * CIN + k0 + kk);
            sXT[kk][r] = v4.x; sXT[kk + 1][r] = v4.y;
            sXT[kk + 2][r] = v4.z; sXT[kk + 3][r] = v4.w;
        }
#pragma unroll
        for (int j = 0; j < 4; j++) {
            int idx = tid + j * 256;
            int kk = idx >> 5;
            int c4 = idx & 31;
            *(float4*)&sW[kk][c4 * 4] =
                *(const float4*)(W + (size_t)(k0 + kk) * COUT + c0 + c4 * 4);
        }
        __syncthreads();
#pragma unroll
        for (int kk = 0; kk < KC; kk++) {
            float4 av = *(const float4*)&sXT[kk][ty * 4];
            float4 bv = *(const float4*)&sW[kk][tx * 4];
            float ar[4] = {av.x, av.y, av.z, av.w};
            float br[4] = {bv.x, bv.y, bv.z, bv.w};
#pragma unroll
            for (int i = 0; i < 4; i++)
#pragma unroll
                for (int j = 0; j < 4; j++)
                    acc[i][j] = fmaf(ar[i], br[j], acc[i][j]);
        }
    }
#pragma unroll
    for (int i = 0; i < 4; i++) {
        int r = ty * 4 + i;
#pragma unroll
        for (int j = 0; j < 4; j++) {
            int c = c0 + tx * 4 + j;
            out[(size_t)r * COUT + c] = acc[i][j] + bW[c];
        }
    }
}

// ---------------------------------------------------------------------------
extern "C" void kernel_launch(void* const* d_in, const int* in_sizes, int n_in,
                              void* d_out, int out_size) {
    const float* query = (const float*)d_in[0];
    const float* VF    = (const float*)d_in[1];
    const float* SF    = (const float*)d_in[2];
    const float* PI    = (const float*)d_in[3];
    const float* W1v   = (const float*)d_in[4];
    const float* W2v   = (const float*)d_in[5];
    const float* vv    = (const float*)d_in[6];
    const float* W3    = (const float*)d_in[7];
    const float* b3    = (const float*)d_in[8];
    const float* W1s   = (const float*)d_in[9];
    const float* W2s   = (const float*)d_in[10];
    const float* vs    = (const float*)d_in[11];
    const float* W     = (const float*)d_in[12];
    const float* bW    = (const float*)d_in[13];
    float* out = (float*)d_out;

    float* base_v_p;  cudaGetSymbolAddress((void**)&base_v_p, g_base_v);
    float* base_s_p;  cudaGetSymbolAddress((void**)&base_s_p, g_base_s);
    float* vscore_p;  cudaGetSymbolAddress((void**)&vscore_p, g_vscores);
    float* sscore_p;  cudaGetSymbolAddress((void**)&sscore_p, g_sscores);

    float* v_attn = out + OUT_VATT_OFF;
    float* s_attn = out + OUT_SATT_OFF;

    cudaFuncSetAttribute(k_scores_mma<FEAT, NV>,
                         cudaFuncAttributeMaxDynamicSharedMemorySize, MM_SMEM_BYTES);
    cudaFuncSetAttribute(k_scores_mma<SEM, NS>,
                         cudaFuncAttributeMaxDynamicSharedMemorySize, MM_SMEM_BYTES);

    k_mean<<<BATCH, DM>>>(PI);
    k_base<<<BATCH, ATTD>>>(query, W1v, W1s, W3, b3);

    k_scores_mma<FEAT, NV><<<(BATCH * NV) / 128, 256, MM_SMEM_BYTES>>>(
        VF, W2v, base_v_p, vv, vscore_p);
    k_scores_mma<SEM, NS><<<(BATCH * NS) / 128, 256, MM_SMEM_BYTES>>>(
        SF, W2s, base_s_p, vs, sscore_p);

    k_softmax<NV><<<BATCH, 256>>>(vscore_p, v_attn);
    k_softmax<NS><<<BATCH, 256>>>(sscore_p, s_attn);

    dim3 gv(FEAT / 256, BATCH);
    k_wsum<NV, FEAT><<<gv, 256>>>(VF, v_attn, 0);
    dim3 gs(SEM / 256, BATCH);
    k_wsum<NS, SEM><<<gs, 256>>>(SF, s_attn, FEAT);

    k_final<<<COUT / 128, 256>>>(W, bW, out + OUT_CTX_OFF);
}

// round 14
// speedup vs baseline: 2.1502x; 1.1638x over previous
#include <cuda_runtime.h>
#include <math.h>
#include <stdint.h>

// Problem dims
#define BATCH 32
#define NV    2048
#define NS    512
#define LSEQ  64
#define FEAT  1024
#define SEM   512
#define HID   512
#define ATTD  512
#define DM    512
#define CIN   (FEAT + SEM)   // 1536
#define COUT  FEAT           // 1024

// Output layout in d_out: ctx [B,1024], v_attn [B,2048], s_attn [B,512]
#define OUT_CTX_OFF   0
#define OUT_VATT_OFF  (BATCH * COUT)                 // 32768
#define OUT_SATT_OFF  (OUT_VATT_OFF + BATCH * NV)    // 98304

// Scratch (device globals; no allocation allowed)
__device__ float g_pm[BATCH * DM];
__device__ float g_base_v[BATCH * ATTD];
__device__ float g_base_s[BATCH * ATTD];
__device__ float g_vpart[4 * BATCH * NV];   // per-N-chunk partial scores
__device__ float g_spart[4 * BATCH * NS];
__device__ float g_ctx[BATCH * CIN];

// ===========================================================================
// mma.sync tf32 helper (portable PTX; HW truncates f32 -> tf32 mantissa)
// ===========================================================================
__device__ __forceinline__ void mma8(float* c, const uint4& a, const uint2& b) {
    asm volatile(
        "mma.sync.aligned.m16n8k8.row.col.f32.tf32.tf32.f32 "
        "{%0,%1,%2,%3}, {%4,%5,%6,%7}, {%8,%9}, {%0,%1,%2,%3};"
        : "+f"(c[0]), "+f"(c[1]), "+f"(c[2]), "+f"(c[3])
        : "r"(a.x), "r"(a.y), "r"(a.z), "r"(a.w), "r"(b.x), "r"(b.y));
}

// SMEM float-offsets (dynamic smem), fragment-major staging
//  As blocks: [mtile(8)*4 + ks(4)] x 132 floats  (32 lanes x 4 regs, pad 4)
//  Bs blocks: [ks(4)*16 + ntile(16)] x 66 floats (32 lanes x 2 regs, pad 2)
#define MM_ASZ  4224            // 32 * 132
#define MM_BSZ  4224            // 64 * 66
#define MM_BUF  (MM_ASZ + MM_BSZ)            // 8448
#define MM_BASE (2 * MM_BUF)                 // 16896 (128 floats: this chunk's base)
#define MM_VV   (MM_BASE + 128)
#define MM_RED  (MM_VV + 128)
#define MM_TOT  (MM_RED + 256)               // 17408 floats
#define MM_SMEM_BYTES (MM_TOT * 4)           // 69632 bytes -> 2 CTAs/SM fit

// ===========================================================================
// Fused score GEMM on tensor cores (mma.sync tf32):
//   part[q, row] = sum_{c in chunk q} tanh( (X @ W2)[row,c] + base[b,c] ) * vv[c]
// Grid: (rows/128, 4 N-chunks). CTA: 256 thr / 8 warps as 4(M)x2(N).
// Each CTA: 128 rows x 128 cols, single K sweep (K chunked by 32, dbl-buffered).
// ===========================================================================
template <int K, int RPB>
__global__ void __launch_bounds__(256, 2)
k_scores_mma(const float* __restrict__ X,     // [M_total, K]
             const float* __restrict__ W2,    // [K, 512] row-major
             const float* __restrict__ base,  // [B, 512]
             const float* __restrict__ vvec,  // [512]
             float* __restrict__ part_out) {  // [4][M_total]
    constexpr int NCK = K / 32;          // K chunks
    extern __shared__ float smf[];

    const int tid = threadIdx.x;
    const int l   = tid & 31;
    const int w   = tid >> 5;
    const int wm  = w & 3;               // M group (32 rows)
    const int wn  = w >> 2;              // N half (64 cols)
    const int row0 = blockIdx.x * 128;
    const int q    = blockIdx.y;         // N chunk
    const int n0   = q * 128;
    const int b = row0 / RPB;

    // stage this chunk's base & vv (128 cols)
    if (tid < 128) {
        smf[MM_BASE + tid] = base[b * ATTD + n0 + tid];
        smf[MM_VV + tid]   = vvec[n0 + tid];
    }

    float acc[16][4];
#pragma unroll
    for (int t = 0; t < 16; t++)
#pragma unroll
        for (int j = 0; j < 4; j++) acc[t][j] = 0.f;

    const float* Xr = X + (size_t)row0 * K;

    // prefetch A chunk 0 (B is loaded at staging time; W2 slice is L2-hot)
    float4 pa[4];
#pragma unroll
    for (int i = 0; i < 4; i++) {
        int idx = tid + i * 256;
        pa[i] = *(const float4*)(Xr + (size_t)(idx >> 3) * K + (idx & 7) * 4);
    }

    for (int it = 0; it < NCK; it++) {
        const int k0 = it * 32;
        float* As = smf + (it & 1) * MM_BUF;
        float* Bs = As + MM_ASZ;

        // ---- store A from prefetch regs (fragment-major scatter) ----
#pragma unroll
        for (int i = 0; i < 4; i++) {
            int idx = tid + i * 256;
            int r = idx >> 3, kq = idx & 7;
            int blk = (r >> 4) * 4 + (kq >> 1);
            int j = ((r & 15) >> 3) | ((kq & 1) << 1);
            float* dst = As + blk * 132 + ((r & 7) << 4) + j;
            dst[0]  = pa[i].x;
            dst[4]  = pa[i].y;
            dst[8]  = pa[i].z;
            dst[12] = pa[i].w;
        }
        // ---- load + store B (fragment-major scatter) ----
#pragma unroll
        for (int i = 0; i < 4; i++) {
            int idx = tid + i * 256;
            int kk = idx >> 5, nq = idx & 31;
            float4 bv = *(const float4*)(W2 + (size_t)(k0 + kk) * ATTD + n0 + nq * 4);
            int j = (kk >> 2) & 1;
            int blk = (kk >> 3) * 16 + (nq >> 1);
            float* dst = Bs + blk * 66 + (nq & 1) * 32 + (kk & 3) * 2 + j;
            dst[0]  = bv.x;
            dst[8]  = bv.y;
            dst[16] = bv.z;
            dst[24] = bv.w;
        }
        __syncthreads();

        // ---- prefetch next A chunk ----
        if (it + 1 < NCK) {
            const int k0n = k0 + 32;
#pragma unroll
            for (int i = 0; i < 4; i++) {
                int idx = tid + i * 256;
                pa[i] = *(const float4*)(Xr + (size_t)(idx >> 3) * K + k0n + (idx & 7) * 4);
            }
        }

        // ---- compute 4 k-steps ----
#pragma unroll
        for (int ks = 0; ks < 4; ks++) {
            const uint4 A0 = *(const uint4*)(As + ((2 * wm) * 4 + ks) * 132 + l * 4);
            const uint4 A1 = *(const uint4*)(As + ((2 * wm + 1) * 4 + ks) * 132 + l * 4);
#pragma unroll
            for (int t = 0; t < 8; t++) {
                const int nt = wn * 8 + t;
                const uint2 Bv = *(const uint2*)(Bs + (ks * 16 + nt) * 66 + l * 2);
                mma8(acc[t],     A0, Bv);
                mma8(acc[8 + t], A1, Bv);
            }
        }
        __syncthreads();   // protect buf reuse 2 its ahead (store side)
    }

    // ---- epilogue: tanh + vv dot over this CTA's 128 cols ----
    float part[4] = {0.f, 0.f, 0.f, 0.f};
#pragma unroll
    for (int t = 0; t < 8; t++) {
        const int n = wn * 64 + t * 8 + (l & 3) * 2;   // local col
        const float2 bs = *(const float2*)(smf + MM_BASE + n);
        const float2 vs = *(const float2*)(smf + MM_VV + n);
        part[0] += tanhf(acc[t][0] + bs.x) * vs.x + tanhf(acc[t][1] + bs.y) * vs.y;
        part[1] += tanhf(acc[t][2] + bs.x) * vs.x + tanhf(acc[t][3] + bs.y) * vs.y;
        part[2] += tanhf(acc[8 + t][0] + bs.x) * vs.x + tanhf(acc[8 + t][1] + bs.y) * vs.y;
        part[3] += tanhf(acc[8 + t][2] + bs.x) * vs.x + tanhf(acc[8 + t][3] + bs.y) * vs.y;
    }
#pragma unroll
    for (int p = 0; p < 4; p++) {
        part[p] += __shfl_xor_sync(0xFFFFFFFFu, part[p], 1);
        part[p] += __shfl_xor_sync(0xFFFFFFFFu, part[p], 2);
    }
    if ((l & 3) == 0) {
#pragma unroll
        for (int p = 0; p < 4; p++) {
            int rl = wm * 32 + (p >> 1) * 16 + (p & 1) * 8 + (l >> 2);
            smf[MM_RED + rl * 2 + wn] = part[p];
        }
    }
    __syncthreads();
    if (tid < 128)
        part_out[(size_t)q * (BATCH * RPB) + row0 + tid] =
            smf[MM_RED + tid * 2] + smf[MM_RED + tid * 2 + 1];
}

// ---------------------------------------------------------------------------
// 1) mean over patient sequence
// ---------------------------------------------------------------------------
__global__ void k_mean(const float* __restrict__ PI) {
    int b = blockIdx.x;
    int d = threadIdx.x;
    const float* p = PI + (size_t)b * LSEQ * DM + d;
    float s = 0.f;
#pragma unroll
    for (int l = 0; l < LSEQ; l++) s += p[(size_t)l * DM];
    g_pm[b * DM + d] = s * (1.0f / LSEQ);
}

// ---------------------------------------------------------------------------
// 2) base vectors
// ---------------------------------------------------------------------------
__global__ void k_base(const float* __restrict__ query,
                       const float* __restrict__ W1v,
                       const float* __restrict__ W1s,
                       const float* __restrict__ W3,
                       const float* __restrict__ b3) {
    int b = blockIdx.x;
    int a = threadIdx.x;                 // 512 threads
    __shared__ float sq[HID];
    __shared__ float sp[DM];
    sq[a] = query[b * HID + a];
    sp[a] = g_pm[b * DM + a];
    __syncthreads();
    float ap = 0.f, av = 0.f, as = 0.f;
#pragma unroll 8
    for (int d = 0; d < DM; d++) {
        float pd = sp[d], qd = sq[d];
        ap = fmaf(pd, W3 [d * ATTD + a], ap);
        av = fmaf(qd, W1v[d * ATTD + a], av);
        as = fmaf(qd, W1s[d * ATTD + a], as);
    }
    float pin = ap + b3[a];
    g_base_v[b * ATTD + a] = pin + av;
    g_base_s[b * ATTD + a] = pin + as;
}

// ---------------------------------------------------------------------------
// 4) softmax over n per batch; sums the 4 N-chunk partials (deterministic)
// ---------------------------------------------------------------------------
template <int N>
__global__ __launch_bounds__(256) void k_softmax(const float* __restrict__ parts,
                                                 float* __restrict__ attn_out) {
    const int PER = N / 256;
    int b = blockIdx.x;
    int tid = threadIdx.x;
    __shared__ float red[8];

    float v[PER];
    float m = -INFINITY;
#pragma unroll
    for (int j = 0; j < PER; j++) {
        int i = b * N + tid + j * 256;
        v[j] = parts[i] + parts[BATCH * N + i] +
               parts[2 * BATCH * N + i] + parts[3 * BATCH * N + i];
        m = fmaxf(m, v[j]);
    }
#pragma unroll
    for (int off = 16; off > 0; off >>= 1)
        m = fmaxf(m, __shfl_xor_sync(0xFFFFFFFFu, m, off));
    if ((tid & 31) == 0) red[tid >> 5] = m;
    __syncthreads();
    m = fmaxf(fmaxf(fmaxf(red[0], red[1]), fmaxf(red[2], red[3])),
              fmaxf(fmaxf(red[4], red[5]), fmaxf(red[6], red[7])));

    float s = 0.f;
#pragma unroll
    for (int j = 0; j < PER; j++) {
        v[j] = expf(v[j] - m);
        s += v[j];
    }
#pragma unroll
    for (int off = 16; off > 0; off >>= 1)
        s += __shfl_xor_sync(0xFFFFFFFFu, s, off);
    __syncthreads();
    if ((tid & 31) == 0) red[tid >> 5] = s;
    __syncthreads();
    s = red[0] + red[1] + red[2] + red[3] + red[4] + red[5] + red[6] + red[7];
    float inv = 1.0f / s;
#pragma unroll
    for (int j = 0; j < PER; j++)
        attn_out[b * N + tid + j * 256] = v[j] * inv;
}

// ---------------------------------------------------------------------------
// 5) attention-weighted sum
// ---------------------------------------------------------------------------
template <int N, int F>
__global__ __launch_bounds__(256) void k_wsum(const float* __restrict__ X,
                                              const float* __restrict__ attn,
                                              int coff) {
    __shared__ float sat[N];
    int b = blockIdx.y;
    int tid = threadIdx.x;
    int f = blockIdx.x * 256 + tid;
#pragma unroll
    for (int j = 0; j < N / 256; j++)
        sat[tid + j * 256] = attn[b * N + tid + j * 256];
    __syncthreads();
    const float* Xb = X + (size_t)b * N * F + f;
    float acc = 0.f;
#pragma unroll 4
    for (int i = 0; i < N; i++)
        acc = fmaf(Xb[(size_t)i * F], sat[i], acc);
    g_ctx[b * CIN + coff + f] = acc;
}

// ---------------------------------------------------------------------------
// 6) final GEMM: out_ctx[32,1024] = g_ctx[32,1536] @ W[1536,1024] + bW
// ---------------------------------------------------------------------------
__global__ __launch_bounds__(256) void k_final(const float* __restrict__ W,
                                               const float* __restrict__ bW,
                                               float* __restrict__ out) {
    const int KC = 32;
    __shared__ float sXT[KC][36];
    __shared__ float sW[KC][128];
    int tid = threadIdx.x;
    int tx = tid & 31, ty = tid >> 5;
    int c0 = blockIdx.x * 128;

    float acc[4][4];
#pragma unroll
    for (int i = 0; i < 4; i++)
#pragma unroll
        for (int j = 0; j < 4; j++) acc[i][j] = 0.f;

    for (int k0 = 0; k0 < CIN; k0 += KC) {
        __syncthreads();
        {
            int r  = tid >> 3;
            int kk = (tid & 7) * 4;
            float4 v4 = *(const float4*)(g_ctx + (size_t)r * CIN + k0 + kk);
            sXT[kk][r] = v4.x; sXT[kk + 1][r] = v4.y;
            sXT[kk + 2][r] = v4.z; sXT[kk + 3][r] = v4.w;
        }
#pragma unroll
        for (int j = 0; j < 4; j++) {
            int idx = tid + j * 256;
            int kk = idx >> 5;
            int c4 = idx & 31;
            *(float4*)&sW[kk][c4 * 4] =
                *(const float4*)(W + (size_t)(k0 + kk) * COUT + c0 + c4 * 4);
        }
        __syncthreads();
#pragma unroll
        for (int kk = 0; kk < KC; kk++) {
            float4 av = *(const float4*)&sXT[kk][ty * 4];
            float4 bv = *(const float4*)&sW[kk][tx * 4];
            float ar[4] = {av.x, av.y, av.z, av.w};
            float br[4] = {bv.x, bv.y, bv.z, bv.w};
#pragma unroll
            for (int i = 0; i < 4; i++)
#pragma unroll
                for (int j = 0; j < 4; j++)
                    acc[i][j] = fmaf(ar[i], br[j], acc[i][j]);
        }
    }
#pragma unroll
    for (int i = 0; i < 4; i++) {
        int r = ty * 4 + i;
#pragma unroll
        for (int j = 0; j < 4; j++) {
            int c = c0 + tx * 4 + j;
            out[(size_t)r * COUT + c] = acc[i][j] + bW[c];
        }
    }
}

// ---------------------------------------------------------------------------
extern "C" void kernel_launch(void* const* d_in, const int* in_sizes, int n_in,
                              void* d_out, int out_size) {
    const float* query = (const float*)d_in[0];
    const float* VF    = (const float*)d_in[1];
    const float* SF    = (const float*)d_in[2];
    const float* PI    = (const float*)d_in[3];
    const float* W1v   = (const float*)d_in[4];
    const float* W2v   = (const float*)d_in[5];
    const float* vv    = (const float*)d_in[6];
    const float* W3    = (const float*)d_in[7];
    const float* b3    = (const float*)d_in[8];
    const float* W1s   = (const float*)d_in[9];
    const float* W2s   = (const float*)d_in[10];
    const float* vs    = (const float*)d_in[11];
    const float* W     = (const float*)d_in[12];
    const float* bW    = (const float*)d_in[13];
    float* out = (float*)d_out;

    float* base_v_p;  cudaGetSymbolAddress((void**)&base_v_p, g_base_v);
    float* base_s_p;  cudaGetSymbolAddress((void**)&base_s_p, g_base_s);
    float* vpart_p;   cudaGetSymbolAddress((void**)&vpart_p, g_vpart);
    float* spart_p;   cudaGetSymbolAddress((void**)&spart_p, g_spart);

    float* v_attn = out + OUT_VATT_OFF;
    float* s_attn = out + OUT_SATT_OFF;

    cudaFuncSetAttribute(k_scores_mma<FEAT, NV>,
                         cudaFuncAttributeMaxDynamicSharedMemorySize, MM_SMEM_BYTES);
    cudaFuncSetAttribute(k_scores_mma<SEM, NS>,
                         cudaFuncAttributeMaxDynamicSharedMemorySize, MM_SMEM_BYTES);

    k_mean<<<BATCH, DM>>>(PI);
    k_base<<<BATCH, ATTD>>>(query, W1v, W1s, W3, b3);

    dim3 gv_sc(BATCH * NV / 128, 4);
    k_scores_mma<FEAT, NV><<<gv_sc, 256, MM_SMEM_BYTES>>>(
        VF, W2v, base_v_p, vv, vpart_p);
    dim3 gs_sc(BATCH * NS / 128, 4);
    k_scores_mma<SEM, NS><<<gs_sc, 256, MM_SMEM_BYTES>>>(
        SF, W2s, base_s_p, vs, spart_p);

    k_softmax<NV><<<BATCH, 256>>>(vpart_p, v_attn);
    k_softmax<NS><<<BATCH, 256>>>(spart_p, s_attn);

    dim3 gv(FEAT / 256, BATCH);
    k_wsum<NV, FEAT><<<gv, 256>>>(VF, v_attn, 0);
    dim3 gs(SEM / 256, BATCH);
    k_wsum<NS, SEM><<<gs, 256>>>(SF, s_attn, FEAT);

    k_final<<<COUT / 128, 256>>>(W, bW, out + OUT_CTX_OFF);
}